// round 1
// baseline (speedup 1.0000x reference)
#include <cuda_runtime.h>
#include <cuda_bf16.h>

#define H 128
#define BASKET_LEN 200
#define NTHREADS 384   // 12 warps

__global__ __launch_bounds__(NTHREADS, 1)
void encoder_rnn_kernel(const int* __restrict__ basket,
                        const float* __restrict__ hidden,
                        const float* __restrict__ emb_table,
                        const float* __restrict__ w_ih,
                        const float* __restrict__ w_hh,
                        const float* __restrict__ b_ih,
                        const float* __restrict__ b_hh,
                        float* __restrict__ out,
                        int out_size)
{
    __shared__ float s_part[NTHREADS];   // gather partials (3 groups x 128 cols)
    __shared__ float s_emb[H];           // averaged embedding
    __shared__ float s_h[H];             // hidden state
    __shared__ float s_g[6 * H];         // gi (3H) then gh (3H)

    const int tid  = threadIdx.x;
    const int col  = tid & (H - 1);
    const int grp  = tid >> 7;           // 0..2
    const int lane = tid & 31;
    const int warp = tid >> 5;           // 0..11

    // ---------- Phase 1: embedding-bag gather-sum (coalesced per row) ----------
    float acc = 0.0f;
    #pragma unroll 4
    for (int i = grp; i < BASKET_LEN; i += 3) {
        long idx = (long)basket[i];
        acc += __ldg(&emb_table[idx * H + col]);
    }
    s_part[tid] = acc;
    if (tid < H) s_h[tid] = hidden[tid];
    __syncthreads();

    if (tid < H) {
        s_emb[tid] = (s_part[tid] + s_part[tid + H] + s_part[tid + 2 * H])
                     * (1.0f / (float)H);
    }
    __syncthreads();

    // ---------- Phase 2: two 384x128 matvecs, warp-per-row, coalesced float4 ----------
    // 768 row-dots total (gi rows 0..383 use s_emb, gh rows 384..767 use s_h).
    // 12 warps x 64 rows each. 384 = 6*64 so each warp is purely gi OR gh.
    {
        const float4 e4 = reinterpret_cast<const float4*>(s_emb)[lane];
        const float4 h4 = reinterpret_cast<const float4*>(s_h)[lane];

        const int rbase = warp * 64;
        const bool is_gi = (rbase < 3 * H);                // uniform per warp
        const float4 v  = is_gi ? e4 : h4;
        const float* W  = is_gi ? w_ih : w_hh;
        const float* B  = is_gi ? b_ih : b_hh;
        const int row0  = is_gi ? rbase : (rbase - 3 * H);

        for (int r = 0; r < 64; r += 4) {
            float part[4];
            #pragma unroll
            for (int j = 0; j < 4; j++) {
                const float4 w4 =
                    reinterpret_cast<const float4*>(W + (size_t)(row0 + r + j) * H)[lane];
                part[j] = w4.x * v.x + w4.y * v.y + w4.z * v.z + w4.w * v.w;
            }
            #pragma unroll
            for (int off = 16; off; off >>= 1) {
                #pragma unroll
                for (int j = 0; j < 4; j++)
                    part[j] += __shfl_xor_sync(0xFFFFFFFFu, part[j], off);
            }
            if (lane < 4) {
                const int rr = row0 + r + lane;
                s_g[rbase + r + lane] = part[lane] + B[rr];
            }
        }
    }
    __syncthreads();

    // ---------- Phase 3: GRU gates + output ----------
    if (tid < H) {
        const float i_r = s_g[tid];
        const float i_z = s_g[H + tid];
        const float i_n = s_g[2 * H + tid];
        const float h_r = s_g[3 * H + tid];
        const float h_z = s_g[4 * H + tid];
        const float h_n = s_g[5 * H + tid];

        const float r = 1.0f / (1.0f + expf(-(i_r + h_r)));
        const float z = 1.0f / (1.0f + expf(-(i_z + h_z)));
        const float n = tanhf(i_n + r * h_n);
        const float h_new = (1.0f - z) * n + z * s_h[tid];

        // reference returns (out, out): replicate across out_size in strides of H
        for (int o = tid; o < out_size; o += H)
            out[o] = h_new;
    }
}

extern "C" void kernel_launch(void* const* d_in, const int* in_sizes, int n_in,
                              void* d_out, int out_size)
{
    const int*   basket    = (const int*)  d_in[0];
    const float* hidden    = (const float*)d_in[1];
    const float* emb_table = (const float*)d_in[2];
    const float* w_ih      = (const float*)d_in[3];
    const float* w_hh      = (const float*)d_in[4];
    const float* b_ih      = (const float*)d_in[5];
    const float* b_hh      = (const float*)d_in[6];
    float* out = (float*)d_out;

    encoder_rnn_kernel<<<1, NTHREADS>>>(basket, hidden, emb_table,
                                        w_ih, w_hh, b_ih, b_hh,
                                        out, out_size);
}

// round 2
// speedup vs baseline: 1.3875x; 1.3875x over previous
#include <cuda_runtime.h>
#include <cuda_bf16.h>

#define H            128
#define BASKET_LEN   200
#define NT           1024          // 32 warps per block
#define WARPS        32
#define GATHER_BLKS  7             // 7*32 = 224 warps >= 200 items
#define NB           (GATHER_BLKS + 1)   // +1 block for gh matvec

// Scratch (device globals; no allocation). All slots written every launch.
__device__ float        g_part[GATHER_BLKS][H];
__device__ float        g_gh[3 * H];
__device__ unsigned int g_ticket;   // zero at load; reset by last block each launch

__global__ __launch_bounds__(NT, 1)
void encoder_rnn_fused(const int* __restrict__ basket,
                       const float* __restrict__ hidden,
                       const float* __restrict__ emb_table,
                       const float* __restrict__ w_ih,
                       const float* __restrict__ w_hh,
                       const float* __restrict__ b_ih,
                       const float* __restrict__ b_hh,
                       float* __restrict__ out,
                       int out_size)
{
    __shared__ float s_red[WARPS * H];      // 16 KB: gather per-warp rows
    __shared__ float s_emb[H];
    __shared__ float s_gi[3 * H];
    __shared__ float s_h[H];
    __shared__ unsigned s_last;

    const int tid  = threadIdx.x;
    const int lane = tid & 31;
    const int w    = tid >> 5;
    const int blk  = blockIdx.x;

    if (blk < GATHER_BLKS) {
        // ---- Phase A: one warp per basket item, full 512B row per LDG.128 ----
        const int item = blk * WARPS + w;
        float4 v = make_float4(0.f, 0.f, 0.f, 0.f);
        if (item < BASKET_LEN) {
            const long idx = (long)__ldg(&basket[item]);
            v = __ldg(&reinterpret_cast<const float4*>(emb_table)[idx * 32 + lane]);
        }
        reinterpret_cast<float4*>(s_red)[w * 32 + lane] = v;
        __syncthreads();
        if (tid < H) {
            float a = 0.f;
            #pragma unroll
            for (int ww = 0; ww < WARPS; ww++) a += s_red[ww * H + tid];
            g_part[blk][tid] = a;
        }
    } else {
        // ---- Phase A': gh = w_hh @ h + b_hh (independent of gather) ----
        const float4 h4 = __ldg(&reinterpret_cast<const float4*>(hidden)[lane]);
        const int r0 = w * 12;                       // 32 warps * 12 rows = 384
        for (int rr = 0; rr < 12; rr += 4) {
            float p0, p1, p2, p3;
            {
                const float4 a = __ldg(&reinterpret_cast<const float4*>(w_hh)[(size_t)(r0 + rr + 0) * 32 + lane]);
                const float4 b = __ldg(&reinterpret_cast<const float4*>(w_hh)[(size_t)(r0 + rr + 1) * 32 + lane]);
                const float4 c = __ldg(&reinterpret_cast<const float4*>(w_hh)[(size_t)(r0 + rr + 2) * 32 + lane]);
                const float4 d = __ldg(&reinterpret_cast<const float4*>(w_hh)[(size_t)(r0 + rr + 3) * 32 + lane]);
                p0 = a.x * h4.x + a.y * h4.y + a.z * h4.z + a.w * h4.w;
                p1 = b.x * h4.x + b.y * h4.y + b.z * h4.z + b.w * h4.w;
                p2 = c.x * h4.x + c.y * h4.y + c.z * h4.z + c.w * h4.w;
                p3 = d.x * h4.x + d.y * h4.y + d.z * h4.z + d.w * h4.w;
            }
            #pragma unroll
            for (int off = 16; off; off >>= 1) {
                p0 += __shfl_xor_sync(0xFFFFFFFFu, p0, off);
                p1 += __shfl_xor_sync(0xFFFFFFFFu, p1, off);
                p2 += __shfl_xor_sync(0xFFFFFFFFu, p2, off);
                p3 += __shfl_xor_sync(0xFFFFFFFFu, p3, off);
            }
            if (lane == 0) {
                g_gh[r0 + rr + 0] = p0 + __ldg(&b_hh[r0 + rr + 0]);
                g_gh[r0 + rr + 1] = p1 + __ldg(&b_hh[r0 + rr + 1]);
                g_gh[r0 + rr + 2] = p2 + __ldg(&b_hh[r0 + rr + 2]);
                g_gh[r0 + rr + 3] = p3 + __ldg(&b_hh[r0 + rr + 3]);
            }
        }
    }

    // ---- Ticket: last-arriving block runs the tail ----
    __threadfence();
    __syncthreads();
    if (tid == 0) s_last = (atomicAdd(&g_ticket, 1u) == NB - 1);
    __syncthreads();
    if (!s_last) return;
    __threadfence();   // acquire: make peers' g_part / g_gh visible

    // ---- Phase B: reduce partials -> emb; load h ----
    if (tid < H) {
        float a = 0.f;
        #pragma unroll
        for (int b = 0; b < GATHER_BLKS; b++) a += g_part[b][tid];
        s_emb[tid] = a * (1.0f / (float)H);
        s_h[tid]   = hidden[tid];
    }
    __syncthreads();

    // ---- Phase C: gi = w_ih @ emb + b_ih (32 warps x 12 rows) ----
    {
        const float4 e4 = reinterpret_cast<const float4*>(s_emb)[lane];
        const int r0 = w * 12;
        for (int rr = 0; rr < 12; rr += 4) {
            float p0, p1, p2, p3;
            {
                const float4 a = __ldg(&reinterpret_cast<const float4*>(w_ih)[(size_t)(r0 + rr + 0) * 32 + lane]);
                const float4 b = __ldg(&reinterpret_cast<const float4*>(w_ih)[(size_t)(r0 + rr + 1) * 32 + lane]);
                const float4 c = __ldg(&reinterpret_cast<const float4*>(w_ih)[(size_t)(r0 + rr + 2) * 32 + lane]);
                const float4 d = __ldg(&reinterpret_cast<const float4*>(w_ih)[(size_t)(r0 + rr + 3) * 32 + lane]);
                p0 = a.x * e4.x + a.y * e4.y + a.z * e4.z + a.w * e4.w;
                p1 = b.x * e4.x + b.y * e4.y + b.z * e4.z + b.w * e4.w;
                p2 = c.x * e4.x + c.y * e4.y + c.z * e4.z + c.w * e4.w;
                p3 = d.x * e4.x + d.y * e4.y + d.z * e4.z + d.w * e4.w;
            }
            #pragma unroll
            for (int off = 16; off; off >>= 1) {
                p0 += __shfl_xor_sync(0xFFFFFFFFu, p0, off);
                p1 += __shfl_xor_sync(0xFFFFFFFFu, p1, off);
                p2 += __shfl_xor_sync(0xFFFFFFFFu, p2, off);
                p3 += __shfl_xor_sync(0xFFFFFFFFu, p3, off);
            }
            if (lane == 0) {
                s_gi[r0 + rr + 0] = p0 + __ldg(&b_ih[r0 + rr + 0]);
                s_gi[r0 + rr + 1] = p1 + __ldg(&b_ih[r0 + rr + 1]);
                s_gi[r0 + rr + 2] = p2 + __ldg(&b_ih[r0 + rr + 2]);
                s_gi[r0 + rr + 3] = p3 + __ldg(&b_ih[r0 + rr + 3]);
            }
        }
    }
    __syncthreads();

    // ---- Phase D: GRU gates + replicated output ----
    if (tid < H) {
        const float i_r = s_gi[tid];
        const float i_z = s_gi[H + tid];
        const float i_n = s_gi[2 * H + tid];
        const float h_r = g_gh[tid];
        const float h_z = g_gh[H + tid];
        const float h_n = g_gh[2 * H + tid];

        const float r = 1.0f / (1.0f + expf(-(i_r + h_r)));
        const float z = 1.0f / (1.0f + expf(-(i_z + h_z)));
        const float n = tanhf(i_n + r * h_n);
        const float h_new = (1.0f - z) * n + z * s_h[tid];

        for (int o = tid; o < out_size; o += H)
            out[o] = h_new;
    }

    if (tid == 0) g_ticket = 0;   // reset for next graph replay
}

extern "C" void kernel_launch(void* const* d_in, const int* in_sizes, int n_in,
                              void* d_out, int out_size)
{
    const int*   basket    = (const int*)  d_in[0];
    const float* hidden    = (const float*)d_in[1];
    const float* emb_table = (const float*)d_in[2];
    const float* w_ih      = (const float*)d_in[3];
    const float* w_hh      = (const float*)d_in[4];
    const float* b_ih      = (const float*)d_in[5];
    const float* b_hh      = (const float*)d_in[6];
    float* out = (float*)d_out;

    encoder_rnn_fused<<<NB, NT>>>(basket, hidden, emb_table,
                                  w_ih, w_hh, b_ih, b_hh,
                                  out, out_size);
}